// round 17
// baseline (speedup 1.0000x reference)
#include <cuda_runtime.h>
#include <cuda_fp16.h>
#include <cstdint>

#define B_ 32
#define T_ 4096
#define H_ 512
#define GRID_ 128
#define THREADS_ 128

// fp16 h image, layout [buf][nq][lane][kt] (8B per (lane,kt) = B-fragment uint2)
__device__ __align__(128) uint32_t g_Bimg[2][8192];    // 32KB per buffer
__device__ float    g_xT[T_ * B_];
__device__ __align__(128) unsigned g_cnt4[128];        // 4 octet counters @ idx 0,32,64,96

__device__ __forceinline__ uint4 ldcg_v4(const void* p) {
    uint4 v;
    asm volatile("ld.global.cg.v4.b32 {%0,%1,%2,%3}, [%4];"
                 : "=r"(v.x), "=r"(v.y), "=r"(v.z), "=r"(v.w) : "l"(p));
    return v;
}
__device__ __forceinline__ void stcg_u16(void* p, unsigned short v) {
    asm volatile("st.global.cg.u16 [%0], %1;" :: "l"(p), "h"(v));
}
__device__ __forceinline__ unsigned ld_acq(const unsigned* p) {
    unsigned v; asm volatile("ld.acquire.gpu.global.u32 %0, [%1];" : "=r"(v) : "l"(p)); return v;
}
__device__ __forceinline__ void red_rel_add1(unsigned* p) {
    asm volatile("red.release.gpu.global.add.u32 [%0], 1;" :: "l"(p));
}
__device__ __forceinline__ float fsig(float x) {
    return __fdividef(1.0f, 1.0f + __expf(-x));
}
__device__ __forceinline__ float ftanh(float x) {
    return 1.0f - __fdividef(2.0f, 1.0f + __expf(2.0f * x));
}
__device__ __forceinline__ uint32_t pack2h(__half e0, __half e1) {
    unsigned short s0 = *(unsigned short*)&e0, s1 = *(unsigned short*)&e1;
    return (uint32_t)s0 | ((uint32_t)s1 << 16);
}

#define HMMA16(d, a, b0r, b1r) \
    asm volatile("mma.sync.aligned.m16n8k16.row.col.f32.f16.f16.f32 " \
        "{%0,%1,%2,%3}, {%4,%5,%6,%7}, {%8,%9}, {%0,%1,%2,%3};" \
        : "+f"(d[0]), "+f"(d[1]), "+f"(d[2]), "+f"(d[3]) \
        : "r"(a[0]), "r"(a[1]), "r"(a[2]), "r"(a[3]), "r"(b0r), "r"(b1r))

__global__ void init_kernel(const float* __restrict__ x) {
    int idx = blockIdx.x * blockDim.x + threadIdx.x;
    int stride = gridDim.x * blockDim.x;
    for (int i = idx; i < 2 * 8192; i += stride) g_Bimg[0][i] = 0u;   // h(-1) = 0
    for (int i = idx; i < T_ * B_; i += stride) {
        int t = i >> 5, b = i & 31;
        g_xT[i] = x[(size_t)b * T_ + t];
    }
    if (idx < 128) g_cnt4[idx] = 0u;
}

__global__ void __launch_bounds__(THREADS_, 1) lstm_kernel(
    const float* __restrict__ Wih,
    const float* __restrict__ Whh,
    const float* __restrict__ bih,
    const float* __restrict__ bhh,
    float* __restrict__ out,
    int write_final)
{
    const int tid  = threadIdx.x;
    const int warp = tid >> 5;     // = nq (batch octet 0..3)
    const int lane = tid & 31;
    const int g    = lane >> 2;    // fragment groupID
    const int tq   = lane & 3;     // fragment threadID_in_group
    const int cta  = blockIdx.x;
    const int nq   = warp;

    // ---- prologue: resident fp16 A fragments (16 gate rows x K512, W-hi only) ----
    uint32_t A[32][4];
#pragma unroll
    for (int kt = 0; kt < 32; kt++) {
        int k0 = kt * 16 + 2 * tq;
#pragma unroll
        for (int rg = 0; rg < 4; rg++) {
            int gr = (rg & 1) ? g + 8 : g;          // gate row 0..15 (= q*4 + u)
            int kk = k0 + ((rg >> 1) ? 8 : 0);
            int q = gr >> 2, u = gr & 3;
            const float* wp = &Whh[(size_t)(q * H_ + cta * 4 + u) * H_ + kk];
            A[kt][rg] = pack2h(__float2half(wp[0]), __float2half(wp[1]));
        }
    }

    // ---- per-lane pointwise identity: (unit u, batch b) ----
    const int bsel = (g >= 4) ? 1 : 0;
    const int b    = 8 * nq + 2 * tq + bsel;
    const int u    = g & 3;
    const int gu   = cta * 4 + u;
    float wih[4], bias[4];
#pragma unroll
    for (int q = 0; q < 4; q++) {
        wih[q]  = Wih[q * H_ + gu];
        bias[q] = bih[q * H_ + gu] + bhh[q * H_ + gu];
    }
    float h_loc = 0.0f, c_loc = 0.0f;

    // publish offset: value h[b][gu] -> fragment position in image
    uint32_t off_h;
    {
        int ktC = gu >> 4, k16 = gu & 15;
        int whichC = k16 >> 3, tq2 = (k16 & 7) >> 1, parC = k16 & 1;
        int laneC = (b & 7) * 4 + tq2;
        off_h = (uint32_t)(nq * 8192 + laneC * 256 + ktC * 8 + whichC * 4 + parC * 2);
    }

    unsigned* mycnt = &g_cnt4[nq * 32];
    const uint32_t lbase = (uint32_t)(nq * 8192 + lane * 256);

    for (int t = 0; t < T_; t++) {
        const int p = t & 1;

        float xv = g_xT[t * B_ + b];   // no gate dependency; load early

        // ---- octet gate: lane0 polls this octet's counter directly ----
        if (lane == 0) {
            const unsigned tgt = (unsigned)GRID_ * (unsigned)t;
            while (ld_acq(mycnt) < tgt) { }
        }
        __syncwarp();

        // ---- B fragments: 16 contiguous LDG.128 per lane + 32 HMMA ----
        const unsigned char* img = (const unsigned char*)g_Bimg[p] + lbase;
        float D[4][4];
#pragma unroll
        for (int j = 0; j < 4; j++)
#pragma unroll
            for (int e = 0; e < 4; e++) D[j][e] = 0.0f;

#pragma unroll
        for (int c = 0; c < 4; c++) {           // chunks of 8 kt (64B per lane)
            uint4 V[4];
#pragma unroll
            for (int i = 0; i < 4; i++) V[i] = ldcg_v4(img + c * 64 + i * 16);
#pragma unroll
            for (int i = 0; i < 4; i++) {
                int kt = c * 8 + 2 * i;
                HMMA16(D[(2 * i) & 3],     A[kt],     V[i].x, V[i].y);
                HMMA16(D[(2 * i + 1) & 3], A[kt + 1], V[i].z, V[i].w);
            }
        }

        // ---- fold 4 accumulator sets ----
        float d0 = (D[0][0] + D[1][0]) + (D[2][0] + D[3][0]);
        float d1 = (D[0][1] + D[1][1]) + (D[2][1] + D[3][1]);
        float d2 = (D[0][2] + D[1][2]) + (D[2][2] + D[3][2]);
        float d3 = (D[0][3] + D[1][3]) + (D[2][3] + D[3][3]);

        // ---- gate exchange: lane pair (g, g+4) swap via shfl.xor(16) ----
        float e0 = __shfl_xor_sync(0xffffffffu, d0, 16);
        float e1 = __shfl_xor_sync(0xffffffffu, d1, 16);
        float e2 = __shfl_xor_sync(0xffffffffu, d2, 16);
        float e3 = __shfl_xor_sync(0xffffffffu, d3, 16);

        float q0, q1, q2, q3;
        if (g < 4) { q0 = d0; q1 = e0; q2 = d2; q3 = e2; }   // col 2tq
        else       { q0 = e1; q1 = d1; q2 = e3; q3 = d3; }   // col 2tq+1

        q0 += fmaf(xv, wih[0], bias[0]);
        q1 += fmaf(xv, wih[1], bias[1]);
        q2 += fmaf(xv, wih[2], bias[2]);
        q3 += fmaf(xv, wih[3], bias[3]);

        // ---- pointwise LSTM + STN blend ----
        float is = fsig(q0);
        float fs = fsig(q1);
        float gs = ftanh(q2);
        float os = fsig(q3);
        float cn = fs * c_loc + is * gs;
        float hn = os * ftanh(cn);
        h_loc = 0.5f * (h_loc + hn);

        // ---- publish h (single fp16) and release this warp ----
        __half hh = __float2half(h_loc);
        stcg_u16((unsigned char*)g_Bimg[p ^ 1] + off_h, *(unsigned short*)&hh);
        __syncwarp();
        if (lane == 0) red_rel_add1(mycnt);

        // ---- off-critical-path epilogue ----
        c_loc = 0.5f * (c_loc + cn);
        {
            float* dst = out + ((size_t)b * T_ + t) * H_ + gu;
            asm volatile("st.global.cs.f32 [%0], %1;" :: "l"(dst), "f"(h_loc));
        }
        if (write_final && t == T_ - 1) {
            float* o2 = out + (size_t)B_ * T_ * H_;
            o2[b * (2 * H_) + gu]      = h_loc;
            o2[b * (2 * H_) + H_ + gu] = c_loc;
        }
    }
}

extern "C" void kernel_launch(void* const* d_in, const int* in_sizes, int n_in,
                              void* d_out, int out_size)
{
    const float* x   = (const float*)d_in[0];
    const float* Wih = (const float*)d_in[1];
    const float* Whh = (const float*)d_in[2];
    const float* bih = (const float*)d_in[3];
    const float* bhh = (const float*)d_in[4];
    float* out = (float*)d_out;

    int need = B_ * T_ * H_ + B_ * 2 * H_;
    int write_final = (out_size >= need) ? 1 : 0;

    init_kernel<<<256, 512>>>(x);
    lstm_kernel<<<GRID_, THREADS_>>>(Wih, Whh, bih, bhh, out, write_final);
}